// round 3
// baseline (speedup 1.0000x reference)
#include <cuda_runtime.h>

#define TILES 800
#define NTHR  320   // 10 warps: warp = k-group (4 ks), lane = pair item

__device__ float  g_z[2 * 400 * 40 * 64];   // pre-IIR projected values (B,T,K,P)
__device__ float  g_cf[2 * 16 * 40 * 64];   // chunk-final y
__device__ float  g_ci[2 * 16 * 40 * 64];   // chunk carry-in
__device__ float2 g_bm[512 * 40];           // interleaved (br,bi) band matrix
__device__ float2 g_ct[64 * 64];            // c2p transposed+interleaved [c][p]

// item table: bits[0:8)=i, [8:16)=j, bit16 = diag-pseudo-pair flag
__constant__ unsigned PAIR_TBL[32] = {
  0x0100,0x0200,0x0300,0x0400,0x0500,0x0600,0x0700,
  0x0201,0x0301,0x0401,0x0501,0x0601,0x0701,
  0x0302,0x0402,0x0502,0x0602,0x0702,
  0x0403,0x0503,0x0603,0x0703,
  0x0504,0x0604,0x0704,
  0x0605,0x0705,
  0x0706,
  0x10100,0x10302,0x10504,0x10706
};

// ---- smem layout (bytes) ----
// prologue: xs float2[8][512] at 0 (32768); gs float2[8][517] at 32768 (33088)
// mainloop: adjA ull[64][32] at 0 (16384); adjB ull[64][32] at 16384 (16384); gs kept
// epilogue: bc float2[40][64] at 0 (20480); invd float[40] at 20480; ct float2[64][65] at 20736 (33280)
#define OFF_XS 0
#define OFF_GS 32768
#define SMEM_TOTAL 65856

__device__ __forceinline__ unsigned long long pack2(float a, float b) {
    unsigned long long r;
    asm("mov.b64 %0, {%1,%2};" : "=l"(r) : "f"(a), "f"(b));
    return r;
}
__device__ __forceinline__ void fma2(unsigned long long& acc,
                                     unsigned long long a, unsigned long long b) {
    asm("fma.rn.f32x2 %0, %1, %2, %0;" : "+l"(acc) : "l"(a), "l"(b));
}
__device__ __forceinline__ void unpack2(unsigned long long x, float& lo, float& hi) {
    asm("mov.b64 {%0,%1}, %2;" : "=f"(lo), "=f"(hi) : "l"(x));
}

extern __shared__ char sm_[];

// ---- prep: build interleaved bm and transposed c2p (runs every launch) ----
__global__ void __launch_bounds__(256) prep(
    const float* __restrict__ bmr, const float* __restrict__ bmi,
    const float* __restrict__ pr,  const float* __restrict__ pi)
{
    int t = blockIdx.x * 256 + threadIdx.x;
    if (t < 20480) {
        g_bm[t] = make_float2(bmr[t], bmi[t]);
    } else {
        int i = t - 20480;
        if (i < 4096) {
            int p = i >> 6, c = i & 63;
            g_ct[c * 64 + p] = make_float2(pr[i], pi[i]);
        }
    }
}

__global__ void __launch_bounds__(NTHR, 3) pv_main(
    const float* __restrict__ br,  const float* __restrict__ bi)
{
    float2* xs = (float2*)(sm_ + OFF_XS);
    float2* gs = (float2*)(sm_ + OFF_GS);

    const int tid  = threadIdx.x;
    const int tile = blockIdx.x;
    const int lane = tid & 31;
    const int w    = tid >> 5;           // warp = k-group (k = 4w..4w+3)

    // ---- Phase A: load bins ----
    const float4* br4 = (const float4*)(br + (size_t)tile * 4096);
    const float4* bi4 = (const float4*)(bi + (size_t)tile * 4096);
    for (int idx = tid; idx < 1024; idx += NTHR) {
        float4 a = br4[idx], b = bi4[idx];
        int o = idx * 4;
        xs[o]   = make_float2(a.x, b.x); xs[o+1] = make_float2(a.y, b.y);
        xs[o+2] = make_float2(a.z, b.z); xs[o+3] = make_float2(a.w, b.w);
    }
    __syncthreads();

    // ---- step 1: per (c,f): (|x|^2, rsqrt) into gs ----
    #pragma unroll
    for (int r = 0; r < 13; r++) {
        int t = tid + r * NTHR;
        if (t < 4096) {
            int c = t >> 9, f = t & 511;
            float2 v = xs[c * 512 + f];
            float n = v.x * v.x + v.y * v.y;
            gs[c * 517 + f] = make_float2(n, rsqrtf(fmaxf(n, 1e-37f)));
        }
    }
    __syncthreads();

    // ---- step 2: trace-normalised amplitude a_c = |x_c| * rsqrt(clip(tr)) ----
    for (int f = tid; f < 512; f += NTHR) {
        float tr = 0.f;
        #pragma unroll
        for (int c = 0; c < 8; c++) tr += gs[c * 517 + f].x;
        float sit = rsqrtf(fmaxf(tr, 1e-20f));
        #pragma unroll
        for (int c = 0; c < 8; c++) {
            float2 v = gs[c * 517 + f];
            gs[c * 517 + f].x = v.x * v.y * sit;   // a = n*rsqrt(n)*sit = |x|*sit
        }
    }
    __syncthreads();

    // ---- step 3: g_c[f] = a_c[f] * r[fm] * r[fp] * conj(x[fm]) * x[fp] ----
    float2 gv[13];
    #pragma unroll
    for (int r = 0; r < 13; r++) {
        int t = tid + r * NTHR;
        if (t < 4096) {
            int c = t >> 9, f = t & 511;
            int fm = min(max(f - 1, 0), 509), fp = fm + 2;
            float a  = gs[c * 517 + f].x;
            float rm = gs[c * 517 + fm].y, rp = gs[c * 517 + fp].y;
            float2 xm = xs[c * 512 + fm], xp = xs[c * 512 + fp];
            float tre = xm.x * xp.x + xm.y * xp.y;
            float tim = xm.x * xp.y - xm.y * xp.x;
            float s = a * rm * rp;
            gv[r] = make_float2(s * tre, s * tim);
        }
    }
    __syncthreads();
    #pragma unroll
    for (int r = 0; r < 13; r++) {
        int t = tid + r * NTHR;
        if (t < 4096) { int c = t >> 9, f = t & 511; gs[c * 517 + f] = gv[r]; }
    }
    __syncthreads();   // xs dead from here

    // ---- main fused loop: adj materialize (64-f chunks) + packed GEMM ----
    const unsigned e = PAIR_TBL[lane];
    const int iCh = e & 255, jCh = (e >> 8) & 255;
    const bool dg = (e & 0x10000u) != 0;

    unsigned long long* adjA = (unsigned long long*)(sm_);          // (u,u)
    unsigned long long* adjB = (unsigned long long*)(sm_ + 16384);  // (v,v)
    const ulonglong2* bm2g = (const ulonglong2*)g_bm;               // 20 per f

    unsigned long long accA0=0, accA1=0, accA2=0, accA3=0;
    unsigned long long accB0=0, accB1=0, accB2=0, accB3=0;

    #pragma unroll 1
    for (int ch = 0; ch < 8; ch++) {
        // adj phase: each thread covers lanes == its own lane (NTHR%32==0)
        #pragma unroll
        for (int r = 0; r < 7; r++) {
            int fc = w + r * 10;
            if (fc < 64) {
                int f = ch * 64 + fc;
                float2 gi = gs[iCh * 517 + f], gj = gs[jCh * 517 + f];
                float u, v;
                if (dg) { u = gi.x*gi.x + gi.y*gi.y;  v = gj.x*gj.x + gj.y*gj.y; }
                else    { u = gi.x*gj.x + gi.y*gj.y;  v = gi.y*gj.x - gi.x*gj.y; }
                adjA[fc * 32 + lane] = pack2(u, u);
                adjB[fc * 32 + lane] = pack2(v, v);
            }
        }
        __syncthreads();

        const int fbase = ch * 64;
        #pragma unroll 4
        for (int fc = 0; fc < 64; fc++) {
            unsigned long long uu = adjA[fc * 32 + lane];
            unsigned long long vv = adjB[fc * 32 + lane];
            int f = fbase + fc;
            ulonglong2 q0 = __ldg(&bm2g[f * 20 + 2 * w]);
            ulonglong2 q1 = __ldg(&bm2g[f * 20 + 2 * w + 1]);
            fma2(accA0, uu, q0.x); fma2(accB0, vv, q0.x);
            fma2(accA1, uu, q0.y); fma2(accB1, vv, q0.y);
            fma2(accA2, uu, q1.x); fma2(accB2, vv, q1.x);
            fma2(accA3, uu, q1.y); fma2(accB3, vv, q1.y);
        }
        __syncthreads();
    }

    // ---- epilogue: assemble band_cov, dsum, cov->pv projection ----
    float2* bc   = (float2*)(sm_);
    float*  invd = (float*)(sm_ + 20480);
    float2* ct   = (float2*)(sm_ + 20736);   // [64][65]

    {
        unsigned long long A[4]  = {accA0, accA1, accA2, accA3};
        unsigned long long Bv[4] = {accB0, accB1, accB2, accB3};
        #pragma unroll
        for (int kk = 0; kk < 4; kk++) {
            float S1, S3, S4, S2;
            unpack2(A[kk], S1, S3);
            unpack2(Bv[kk], S4, S2);
            int k = 4 * w + kk;
            if (dg) {
                bc[k * 64 + iCh * 9] = make_float2(S1, S3);
                bc[k * 64 + jCh * 9] = make_float2(S4, S2);
            } else {
                bc[k * 64 + iCh * 8 + jCh] = make_float2(S1 - S2, S3 + S4);
                bc[k * 64 + jCh * 8 + iCh] = make_float2(S1 + S2, S3 - S4);
            }
        }
    }
    __syncthreads();

    if (tid < 40) {
        float s = 0.f;
        #pragma unroll
        for (int d = 0; d < 8; d++) s += bc[tid * 64 + d * 9].x;
        invd[tid] = 1.0f / fmaxf(s, 1e-20f);
    }
    for (int idx = tid; idx < 4096; idx += NTHR) {
        int c = idx >> 6, p = idx & 63;
        ct[c * 65 + p] = g_ct[idx];
    }
    __syncthreads();

    const unsigned long long* ctu = (const unsigned long long*)ct;
    const unsigned long long* bcu = (const unsigned long long*)bc;
    const int p  = tid & 63;
    const int kq = tid >> 6;         // 0..4, warp-uniform
    unsigned long long acc[8] = {0,0,0,0,0,0,0,0};
    #pragma unroll 4
    for (int c = 0; c < 64; c++) {
        unsigned long long m = ctu[c * 65 + p];
        #pragma unroll
        for (int r = 0; r < 8; r++)
            fma2(acc[r], m, bcu[(kq + 5 * r) * 64 + c]);
    }
    float* zt = g_z + (size_t)tile * 2560;
    #pragma unroll
    for (int r = 0; r < 8; r++) {
        int k = kq + 5 * r;
        float lo, hi; unpack2(acc[r], lo, hi);
        zt[k * 64 + p] = (lo - hi) * invd[k];   // Re(c2p·y) / dsum
    }
}

// ---- IIR as blocked scan: 16 chunks of 25 frames ----
__global__ void __launch_bounds__(256) iir_local(const float* __restrict__ tau,
                                                 float* __restrict__ out)
{
    int tid = blockIdx.x * 256 + threadIdx.x;   // 81920 = B*16*K*P
    int p = tid & 63;
    int k = (tid >> 6) % 40;
    int ch = (tid / 2560) & 15;
    int b = tid / 40960;
    float a = tau[k], om = 1.0f - a;
    size_t base = ((size_t)b * 400 + ch * 25) * 2560 + k * 64 + p;
    float y = 0.f;
    #pragma unroll 5
    for (int i = 0; i < 25; i++) {
        y = a * y + om * g_z[base + (size_t)i * 2560];
        out[base + (size_t)i * 2560] = y;
    }
    g_cf[((b * 16 + ch) * 40 + k) * 64 + p] = y;
}

__global__ void __launch_bounds__(256) iir_carry(const float* __restrict__ tau)
{
    int tid = blockIdx.x * 256 + threadIdx.x;   // 5120 = B*K*P
    int p = tid & 63, k = (tid >> 6) % 40, b = tid / 2560;
    float a = tau[k];
    float a25 = powf(a, 25.f);
    float prev = 0.f;
    #pragma unroll
    for (int ch = 0; ch < 16; ch++) {
        int idx = ((b * 16 + ch) * 40 + k) * 64 + p;
        g_ci[idx] = prev;
        prev = g_cf[idx] + a25 * prev;
    }
}

__global__ void __launch_bounds__(256) iir_fix(const float* __restrict__ tau,
                                               float* __restrict__ out)
{
    int tid = blockIdx.x * 256 + threadIdx.x;
    int p = tid & 63, k = (tid >> 6) % 40;
    int ch = (tid / 2560) & 15, b = tid / 40960;
    if (ch == 0) return;
    float c = g_ci[((b * 16 + ch) * 40 + k) * 64 + p];
    float a = tau[k];
    size_t base = ((size_t)b * 400 + ch * 25) * 2560 + k * 64 + p;
    float t = a * c;
    #pragma unroll 5
    for (int i = 0; i < 25; i++) {
        out[base + (size_t)i * 2560] += t;   // y = local + c * a^(i+1)
        t *= a;
    }
}

extern "C" void kernel_launch(void* const* d_in, const int* in_sizes, int n_in,
                              void* d_out, int out_size)
{
    const float* br  = (const float*)d_in[0];
    const float* bi  = (const float*)d_in[1];
    const float* bmr = (const float*)d_in[2];
    const float* bmi = (const float*)d_in[3];
    const float* pr  = (const float*)d_in[4];
    const float* pi  = (const float*)d_in[5];
    const float* tau = (const float*)d_in[6];

    cudaFuncSetAttribute(pv_main, cudaFuncAttributeMaxDynamicSharedMemorySize, SMEM_TOTAL);

    prep<<<96, 256>>>(bmr, bmi, pr, pi);
    pv_main<<<TILES, NTHR, SMEM_TOTAL>>>(br, bi);
    iir_local<<<320, 256>>>(tau, (float*)d_out);
    iir_carry<<<20, 256>>>(tau);
    iir_fix<<<320, 256>>>(tau, (float*)d_out);
}

// round 4
// speedup vs baseline: 1.3046x; 1.3046x over previous
#include <cuda_runtime.h>

#define TILES 800
#define NTHR  320   // 10 warps: warp = k-group (4 ks), lane = pair item

__device__ float  g_z[2 * 400 * 40 * 64];   // pre-IIR projected values (B,T,K,P)
__device__ float  g_cf[2 * 16 * 40 * 64];   // chunk-final y
__device__ float  g_ci[2 * 16 * 40 * 64];   // chunk carry-in
__device__ float2 g_bm[512 * 40];           // interleaved (br,bi) band matrix
__device__ float2 g_ct[64 * 64];            // c2p transposed+interleaved [c][p]

// item table: bits[0:8)=i, [8:16)=j, bit16 = diag-pseudo-pair flag
__constant__ unsigned PAIR_TBL[32] = {
  0x0100,0x0200,0x0300,0x0400,0x0500,0x0600,0x0700,
  0x0201,0x0301,0x0401,0x0501,0x0601,0x0701,
  0x0302,0x0402,0x0502,0x0602,0x0702,
  0x0403,0x0503,0x0603,0x0703,
  0x0504,0x0604,0x0704,
  0x0605,0x0705,
  0x0706,
  0x10100,0x10302,0x10504,0x10706
};

// ---- smem layout (bytes) ----
// [0,32768)       prologue: xs float2[8][512];  mainloop: adjA/adjB ull[64][32] each 16KB
//                 epilogue: bc[40][64]f2 (20480) | invd (160@20480) | ct[64][65]f2 (@20736)
// [32768,73728)   bm double buffer: 2 x 20480 (64f x 40k float2 chunks)
// [73728,106816)  gs float2[8][517]
#define OFF_ADJ 0
#define OFF_BM  32768
#define OFF_GS  73728
#define SMEM_TOTAL 106816

__device__ __forceinline__ unsigned long long pack2(float a, float b) {
    unsigned long long r;
    asm("mov.b64 %0, {%1,%2};" : "=l"(r) : "f"(a), "f"(b));
    return r;
}
__device__ __forceinline__ void fma2(unsigned long long& acc,
                                     unsigned long long a, unsigned long long b) {
    asm("fma.rn.f32x2 %0, %1, %2, %0;" : "+l"(acc) : "l"(a), "l"(b));
}
__device__ __forceinline__ void unpack2(unsigned long long x, float& lo, float& hi) {
    asm("mov.b64 {%0,%1}, %2;" : "=f"(lo), "=f"(hi) : "l"(x));
}

extern __shared__ char sm_[];

// issue one 20480B bm chunk (64 f) into smem buffer via cp.async
__device__ __forceinline__ void issue_bm_chunk(unsigned sdst_base, int buf, int ch, int tid) {
    unsigned long long src = (unsigned long long)__cvta_generic_to_global(
        (const char*)g_bm + (size_t)ch * 20480 + (size_t)tid * 16);
    unsigned dst = sdst_base + OFF_BM + buf * 20480 + tid * 16;
    #pragma unroll
    for (int r = 0; r < 4; r++) {
        asm volatile("cp.async.cg.shared.global [%0], [%1], 16;"
                     :: "r"(dst + r * 5120), "l"(src + r * 5120));
    }
}

// ---- prep: build interleaved bm and transposed c2p (runs every launch) ----
__global__ void __launch_bounds__(256) prep(
    const float* __restrict__ bmr, const float* __restrict__ bmi,
    const float* __restrict__ pr,  const float* __restrict__ pi)
{
    int t = blockIdx.x * 256 + threadIdx.x;
    if (t < 20480) {
        g_bm[t] = make_float2(bmr[t], bmi[t]);
    } else {
        int i = t - 20480;
        if (i < 4096) {
            int p = i >> 6, c = i & 63;
            g_ct[c * 64 + p] = make_float2(pr[i], pi[i]);
        }
    }
}

__global__ void __launch_bounds__(NTHR, 2) pv_main(
    const float* __restrict__ br,  const float* __restrict__ bi)
{
    float2* xs = (float2*)(sm_ + OFF_ADJ);
    float2* gs = (float2*)(sm_ + OFF_GS);
    const unsigned sbase = (unsigned)__cvta_generic_to_shared(sm_);

    const int tid  = threadIdx.x;
    const int tile = blockIdx.x;
    const int lane = tid & 31;
    const int w    = tid >> 5;           // warp = k-group (k = 4w..4w+3)

    // kick off bm chunk 0 immediately — overlaps the whole prologue
    issue_bm_chunk(sbase, 0, 0, tid);
    asm volatile("cp.async.commit_group;");

    // ---- Phase A: load bins ----
    const float4* br4 = (const float4*)(br + (size_t)tile * 4096);
    const float4* bi4 = (const float4*)(bi + (size_t)tile * 4096);
    for (int idx = tid; idx < 1024; idx += NTHR) {
        float4 a = br4[idx], b = bi4[idx];
        int o = idx * 4;
        xs[o]   = make_float2(a.x, b.x); xs[o+1] = make_float2(a.y, b.y);
        xs[o+2] = make_float2(a.z, b.z); xs[o+3] = make_float2(a.w, b.w);
    }
    __syncthreads();

    // ---- step 1: per (c,f): (|x|^2, rsqrt) into gs ----
    #pragma unroll
    for (int r = 0; r < 13; r++) {
        int t = tid + r * NTHR;
        if (t < 4096) {
            int c = t >> 9, f = t & 511;
            float2 v = xs[c * 512 + f];
            float n = v.x * v.x + v.y * v.y;
            gs[c * 517 + f] = make_float2(n, rsqrtf(fmaxf(n, 1e-37f)));
        }
    }
    __syncthreads();

    // ---- step 2: trace-normalised amplitude a_c = |x_c| * rsqrt(clip(tr)) ----
    for (int f = tid; f < 512; f += NTHR) {
        float tr = 0.f;
        #pragma unroll
        for (int c = 0; c < 8; c++) tr += gs[c * 517 + f].x;
        float sit = rsqrtf(fmaxf(tr, 1e-20f));
        #pragma unroll
        for (int c = 0; c < 8; c++) {
            float2 v = gs[c * 517 + f];
            gs[c * 517 + f].x = v.x * v.y * sit;   // a = n*rsqrt(n)*sit = |x|*sit
        }
    }
    __syncthreads();

    // ---- step 3: g_c[f] = a_c[f] * r[fm] * r[fp] * conj(x[fm]) * x[fp] ----
    float2 gv[13];
    #pragma unroll
    for (int r = 0; r < 13; r++) {
        int t = tid + r * NTHR;
        if (t < 4096) {
            int c = t >> 9, f = t & 511;
            int fm = min(max(f - 1, 0), 509), fp = fm + 2;
            float a  = gs[c * 517 + f].x;
            float rm = gs[c * 517 + fm].y, rp = gs[c * 517 + fp].y;
            float2 xm = xs[c * 512 + fm], xp = xs[c * 512 + fp];
            float tre = xm.x * xp.x + xm.y * xp.y;
            float tim = xm.x * xp.y - xm.y * xp.x;
            float s = a * rm * rp;
            gv[r] = make_float2(s * tre, s * tim);
        }
    }
    __syncthreads();
    #pragma unroll
    for (int r = 0; r < 13; r++) {
        int t = tid + r * NTHR;
        if (t < 4096) { int c = t >> 9, f = t & 511; gs[c * 517 + f] = gv[r]; }
    }
    __syncthreads();   // xs dead from here; adj reuses its space

    // ---- main fused loop: adj materialize + double-buffered bm + packed GEMM ----
    const unsigned e = PAIR_TBL[lane];
    const int iCh = e & 255, jCh = (e >> 8) & 255;
    const bool dg = (e & 0x10000u) != 0;

    unsigned long long* adjA = (unsigned long long*)(sm_ + OFF_ADJ);          // (u,u)
    unsigned long long* adjB = (unsigned long long*)(sm_ + OFF_ADJ + 16384);  // (v,v)

    unsigned long long accA0=0, accA1=0, accA2=0, accA3=0;
    unsigned long long accB0=0, accB1=0, accB2=0, accB3=0;

    int buf = 0;
    #pragma unroll 1
    for (int ch = 0; ch < 8; ch++) {
        // adj phase for chunk ch (reads gs only)
        #pragma unroll
        for (int r = 0; r < 7; r++) {
            int fc = w + r * 10;
            if (fc < 64) {
                int f = ch * 64 + fc;
                float2 gi = gs[iCh * 517 + f], gj = gs[jCh * 517 + f];
                float u, v;
                if (dg) { u = gi.x*gi.x + gi.y*gi.y;  v = gj.x*gj.x + gj.y*gj.y; }
                else    { u = gi.x*gj.x + gi.y*gj.y;  v = gi.y*gj.x - gi.x*gj.y; }
                adjA[fc * 32 + lane] = pack2(u, u);
                adjB[fc * 32 + lane] = pack2(v, v);
            }
        }
        // prefetch next chunk into the other buffer
        if (ch + 1 < 8) issue_bm_chunk(sbase, buf ^ 1, ch + 1, tid);
        asm volatile("cp.async.commit_group;");
        asm volatile("cp.async.wait_group 1;");   // chunk ch resident
        __syncthreads();

        const ulonglong2* bmc = (const ulonglong2*)(sm_ + OFF_BM + buf * 20480);
        #pragma unroll 4
        for (int fc = 0; fc < 64; fc++) {
            unsigned long long uu = adjA[fc * 32 + lane];
            unsigned long long vv = adjB[fc * 32 + lane];
            ulonglong2 q0 = bmc[fc * 20 + 2 * w];
            ulonglong2 q1 = bmc[fc * 20 + 2 * w + 1];
            fma2(accA0, uu, q0.x); fma2(accB0, vv, q0.x);
            fma2(accA1, uu, q0.y); fma2(accB1, vv, q0.y);
            fma2(accA2, uu, q1.x); fma2(accB2, vv, q1.x);
            fma2(accA3, uu, q1.y); fma2(accB3, vv, q1.y);
        }
        buf ^= 1;
        __syncthreads();
    }

    // ---- epilogue: assemble band_cov, dsum, cov->pv projection ----
    float2* bc   = (float2*)(sm_);
    float*  invd = (float*)(sm_ + 20480);
    float2* ct   = (float2*)(sm_ + 20736);   // [64][65]

    {
        unsigned long long A[4]  = {accA0, accA1, accA2, accA3};
        unsigned long long Bv[4] = {accB0, accB1, accB2, accB3};
        #pragma unroll
        for (int kk = 0; kk < 4; kk++) {
            float S1, S3, S4, S2;
            unpack2(A[kk], S1, S3);
            unpack2(Bv[kk], S4, S2);
            int k = 4 * w + kk;
            if (dg) {
                bc[k * 64 + iCh * 9] = make_float2(S1, S3);
                bc[k * 64 + jCh * 9] = make_float2(S4, S2);
            } else {
                bc[k * 64 + iCh * 8 + jCh] = make_float2(S1 - S2, S3 + S4);
                bc[k * 64 + jCh * 8 + iCh] = make_float2(S1 + S2, S3 - S4);
            }
        }
    }
    __syncthreads();

    if (tid < 40) {
        float s = 0.f;
        #pragma unroll
        for (int d = 0; d < 8; d++) s += bc[tid * 64 + d * 9].x;
        invd[tid] = 1.0f / fmaxf(s, 1e-20f);
    }
    for (int idx = tid; idx < 4096; idx += NTHR) {
        int c = idx >> 6, p = idx & 63;
        ct[c * 65 + p] = g_ct[idx];
    }
    __syncthreads();

    const unsigned long long* ctu = (const unsigned long long*)ct;
    const unsigned long long* bcu = (const unsigned long long*)bc;
    const int p  = tid & 63;
    const int kq = tid >> 6;         // 0..4, warp-uniform
    unsigned long long acc[8] = {0,0,0,0,0,0,0,0};
    #pragma unroll 4
    for (int c = 0; c < 64; c++) {
        unsigned long long m = ctu[c * 65 + p];
        #pragma unroll
        for (int r = 0; r < 8; r++)
            fma2(acc[r], m, bcu[(kq + 5 * r) * 64 + c]);
    }
    float* zt = g_z + (size_t)tile * 2560;
    #pragma unroll
    for (int r = 0; r < 8; r++) {
        int k = kq + 5 * r;
        float lo, hi; unpack2(acc[r], lo, hi);
        zt[k * 64 + p] = (lo - hi) * invd[k];   // Re(c2p·y) / dsum
    }
}

// ---- IIR as blocked scan: 16 chunks of 25 frames ----
__global__ void __launch_bounds__(256) iir_local(const float* __restrict__ tau,
                                                 float* __restrict__ out)
{
    int tid = blockIdx.x * 256 + threadIdx.x;   // 81920 = B*16*K*P
    int p = tid & 63;
    int k = (tid >> 6) % 40;
    int ch = (tid / 2560) & 15;
    int b = tid / 40960;
    float a = tau[k], om = 1.0f - a;
    size_t base = ((size_t)b * 400 + ch * 25) * 2560 + k * 64 + p;
    float y = 0.f;
    #pragma unroll 5
    for (int i = 0; i < 25; i++) {
        y = a * y + om * g_z[base + (size_t)i * 2560];
        out[base + (size_t)i * 2560] = y;
    }
    g_cf[((b * 16 + ch) * 40 + k) * 64 + p] = y;
}

__global__ void __launch_bounds__(256) iir_carry(const float* __restrict__ tau)
{
    int tid = blockIdx.x * 256 + threadIdx.x;   // 5120 = B*K*P
    int p = tid & 63, k = (tid >> 6) % 40, b = tid / 2560;
    float a = tau[k];
    float a2 = a * a, a4 = a2 * a2, a8 = a4 * a4, a16 = a8 * a8;
    float a25 = a16 * a8 * a;
    // prefetch all chunk finals (MLP=16), then run the serial combine
    float cf[16];
    #pragma unroll
    for (int ch = 0; ch < 16; ch++)
        cf[ch] = g_cf[((b * 16 + ch) * 40 + k) * 64 + p];
    float prev = 0.f;
    #pragma unroll
    for (int ch = 0; ch < 16; ch++) {
        g_ci[((b * 16 + ch) * 40 + k) * 64 + p] = prev;
        prev = cf[ch] + a25 * prev;
    }
}

__global__ void __launch_bounds__(256) iir_fix(const float* __restrict__ tau,
                                               float* __restrict__ out)
{
    int tid = blockIdx.x * 256 + threadIdx.x;
    int p = tid & 63, k = (tid >> 6) % 40;
    int ch = (tid / 2560) & 15, b = tid / 40960;
    if (ch == 0) return;
    float c = g_ci[((b * 16 + ch) * 40 + k) * 64 + p];
    float a = tau[k];
    size_t base = ((size_t)b * 400 + ch * 25) * 2560 + k * 64 + p;
    float t = a * c;
    #pragma unroll 5
    for (int i = 0; i < 25; i++) {
        out[base + (size_t)i * 2560] += t;   // y = local + c * a^(i+1)
        t *= a;
    }
}

extern "C" void kernel_launch(void* const* d_in, const int* in_sizes, int n_in,
                              void* d_out, int out_size)
{
    const float* br  = (const float*)d_in[0];
    const float* bi  = (const float*)d_in[1];
    const float* bmr = (const float*)d_in[2];
    const float* bmi = (const float*)d_in[3];
    const float* pr  = (const float*)d_in[4];
    const float* pi  = (const float*)d_in[5];
    const float* tau = (const float*)d_in[6];

    cudaFuncSetAttribute(pv_main, cudaFuncAttributeMaxDynamicSharedMemorySize, SMEM_TOTAL);

    prep<<<96, 256>>>(bmr, bmi, pr, pi);
    pv_main<<<TILES, NTHR, SMEM_TOTAL>>>(br, bi);
    iir_local<<<320, 256>>>(tau, (float*)d_out);
    iir_carry<<<20, 256>>>(tau);
    iir_fix<<<320, 256>>>(tau, (float*)d_out);
}

// round 5
// speedup vs baseline: 1.5757x; 1.2077x over previous
#include <cuda_runtime.h>

#define TILES 800
#define NTHR  320   // 10 warps: warp = k-group (4 ks), lane = pair item

__device__ float  g_z[2 * 400 * 40 * 64];   // pre-IIR projected values (B,T,K,P)
__device__ float  g_cf[2 * 16 * 40 * 64];   // chunk-final y
__device__ float  g_ci[2 * 16 * 40 * 64];   // chunk carry-in
__device__ __align__(16) float2 g_bm[512 * 40];  // interleaved (br,bi) band matrix
__device__ __align__(16) float2 g_ct[64 * 64];   // c2p transposed [c][p]

// item table: bits[0:8)=i, [8:16)=j, bit16 = diag-pseudo-pair flag
__constant__ unsigned PAIR_TBL[32] = {
  0x0100,0x0200,0x0300,0x0400,0x0500,0x0600,0x0700,
  0x0201,0x0301,0x0401,0x0501,0x0601,0x0701,
  0x0302,0x0402,0x0502,0x0602,0x0702,
  0x0403,0x0503,0x0603,0x0703,
  0x0504,0x0604,0x0704,
  0x0605,0x0705,
  0x0706,
  0x10100,0x10302,0x10504,0x10706
};

// ---- smem layout (bytes) ----
// [0,32768)       prologue: brs float[4096] @0, bis float[4096] @16384
//                 mainloop: adj float2[64][32] @0 (16384)
//                 epilogue: bc[40][64]f2 @0 (20480) | invd @20480 | ct[64][65]f2 @20736 (33280)
// [32768,73728)   bm double buffer: 2 x 20480 (64f x 40k float2 chunks)
// [73728,106816)  gs float2[8][517]
// [106816,106848) mbarriers: mb_x @ +0, mb_bm0 @ +8, mb_bm1 @ +16
#define OFF_BRS 0
#define OFF_BIS 16384
#define OFF_BM  32768
#define OFF_GS  73728
#define OFF_MB  106816
#define SMEM_TOTAL 106848

__device__ __forceinline__ unsigned long long pack2(float a, float b) {
    unsigned long long r;
    asm("mov.b64 %0, {%1,%2};" : "=l"(r) : "f"(a), "f"(b));
    return r;
}
__device__ __forceinline__ void fma2(unsigned long long& acc,
                                     unsigned long long a, unsigned long long b) {
    asm("fma.rn.f32x2 %0, %1, %2, %0;" : "+l"(acc) : "l"(a), "l"(b));
}
__device__ __forceinline__ void unpack2(unsigned long long x, float& lo, float& hi) {
    asm("mov.b64 {%0,%1}, %2;" : "=f"(lo), "=f"(hi) : "l"(x));
}

__device__ __forceinline__ void mbar_init(unsigned mbar, unsigned cnt) {
    asm volatile("mbarrier.init.shared.b64 [%0], %1;" :: "r"(mbar), "r"(cnt) : "memory");
}
__device__ __forceinline__ void mbar_expect(unsigned mbar, unsigned bytes) {
    asm volatile("mbarrier.arrive.expect_tx.shared.b64 _, [%0], %1;"
                 :: "r"(mbar), "r"(bytes) : "memory");
}
__device__ __forceinline__ void bulk_g2s(unsigned dst, const void* src,
                                         unsigned bytes, unsigned mbar) {
    asm volatile("cp.async.bulk.shared::cluster.global.mbarrier::complete_tx::bytes "
                 "[%0], [%1], %2, [%3];"
                 :: "r"(dst), "l"(src), "r"(bytes), "r"(mbar) : "memory");
}
__device__ __forceinline__ void mbar_wait(unsigned mbar, unsigned parity) {
    asm volatile(
        "{\n\t.reg .pred P1;\n\t"
        "WL_%=:\n\t"
        "mbarrier.try_wait.parity.acquire.cta.shared::cta.b64 P1, [%0], %1, 0x989680;\n\t"
        "@P1 bra.uni WD_%=;\n\t"
        "bra.uni WL_%=;\n\t"
        "WD_%=:\n\t}"
        :: "r"(mbar), "r"(parity) : "memory");
}

extern __shared__ char sm_[];

// ---- prep: build interleaved bm and transposed c2p (runs every launch) ----
__global__ void __launch_bounds__(256) prep(
    const float* __restrict__ bmr, const float* __restrict__ bmi,
    const float* __restrict__ pr,  const float* __restrict__ pi)
{
    int t = blockIdx.x * 256 + threadIdx.x;
    if (t < 20480) {
        g_bm[t] = make_float2(bmr[t], bmi[t]);
    } else {
        int i = t - 20480;
        if (i < 4096) {
            int p = i >> 6, c = i & 63;
            g_ct[c * 64 + p] = make_float2(pr[i], pi[i]);
        }
    }
}

__global__ void __launch_bounds__(NTHR, 2) pv_main(
    const float* __restrict__ br,  const float* __restrict__ bi)
{
    float*  brs = (float*)(sm_ + OFF_BRS);
    float*  bis = (float*)(sm_ + OFF_BIS);
    float2* gs  = (float2*)(sm_ + OFF_GS);
    const unsigned sbase = (unsigned)__cvta_generic_to_shared(sm_);
    const unsigned mb_x  = sbase + OFF_MB;
    const unsigned mb_bm0 = sbase + OFF_MB + 8;
    const unsigned mb_bm1 = sbase + OFF_MB + 16;

    const int tid  = threadIdx.x;
    const int tile = blockIdx.x;
    const int lane = tid & 31;
    const int w    = tid >> 5;           // warp = k-group (k = 4w..4w+3)

    // ---- init mbarriers, then kick off all initial bulk copies ----
    if (tid == 0) {
        mbar_init(mb_x, 1);
        mbar_init(mb_bm0, 1);
        mbar_init(mb_bm1, 1);
        asm volatile("fence.proxy.async.shared::cta;" ::: "memory");
    }
    __syncthreads();
    if (tid == 0) {
        mbar_expect(mb_x, 32768);
        bulk_g2s(sbase + OFF_BRS, br + (size_t)tile * 4096, 16384, mb_x);
        bulk_g2s(sbase + OFF_BIS, bi + (size_t)tile * 4096, 16384, mb_x);
        mbar_expect(mb_bm0, 20480);
        bulk_g2s(sbase + OFF_BM, (const char*)g_bm, 20480, mb_bm0);
        mbar_expect(mb_bm1, 20480);
        bulk_g2s(sbase + OFF_BM + 20480, (const char*)g_bm + 20480, 20480, mb_bm1);
    }
    mbar_wait(mb_x, 0);

    // ---- step 1: per (c,f): (|x|^2, rsqrt) into gs ----
    #pragma unroll
    for (int r = 0; r < 13; r++) {
        int t = tid + r * NTHR;
        if (t < 4096) {
            int c = t >> 9, f = t & 511;
            float re = brs[t], im = bis[t];
            float n = re * re + im * im;
            gs[c * 517 + f] = make_float2(n, rsqrtf(fmaxf(n, 1e-37f)));
        }
    }
    __syncthreads();

    // ---- step 2: trace-normalised amplitude a_c = |x_c| * rsqrt(clip(tr)) ----
    for (int f = tid; f < 512; f += NTHR) {
        float tr = 0.f;
        #pragma unroll
        for (int c = 0; c < 8; c++) tr += gs[c * 517 + f].x;
        float sit = rsqrtf(fmaxf(tr, 1e-20f));
        #pragma unroll
        for (int c = 0; c < 8; c++) {
            float2 v = gs[c * 517 + f];
            gs[c * 517 + f].x = v.x * v.y * sit;   // a = n*rsqrt(n)*sit = |x|*sit
        }
    }
    __syncthreads();

    // ---- step 3: g_c[f] = a_c[f] * r[fm] * r[fp] * conj(x[fm]) * x[fp] ----
    float2 gv[13];
    #pragma unroll
    for (int r = 0; r < 13; r++) {
        int t = tid + r * NTHR;
        if (t < 4096) {
            int c = t >> 9, f = t & 511;
            int fm = min(max(f - 1, 0), 509), fp = fm + 2;
            float a  = gs[c * 517 + f].x;
            float rm = gs[c * 517 + fm].y, rp = gs[c * 517 + fp].y;
            float xmr = brs[c * 512 + fm], xmi = bis[c * 512 + fm];
            float xpr = brs[c * 512 + fp], xpi = bis[c * 512 + fp];
            float tre = xmr * xpr + xmi * xpi;
            float tim = xmr * xpi - xmi * xpr;
            float s = a * rm * rp;
            gv[r] = make_float2(s * tre, s * tim);
        }
    }
    __syncthreads();
    #pragma unroll
    for (int r = 0; r < 13; r++) {
        int t = tid + r * NTHR;
        if (t < 4096) { int c = t >> 9, f = t & 511; gs[c * 517 + f] = gv[r]; }
    }
    // brs/bis dead from here; adj reuses [0,16384)

    // ---- main fused loop: adj materialize + TMA double-buffered bm + GEMM ----
    const unsigned e = PAIR_TBL[lane];
    const int iCh = e & 255, jCh = (e >> 8) & 255;
    const bool dg = (e & 0x10000u) != 0;

    float2* adj = (float2*)(sm_);

    unsigned long long accA0=0, accA1=0, accA2=0, accA3=0;
    unsigned long long accB0=0, accB1=0, accB2=0, accB3=0;

    #pragma unroll 1
    for (int ch = 0; ch < 8; ch++) {
        __syncthreads();   // GEMM(ch-1) done: adj free, bm buf((ch+1)&1) free
        if (ch >= 1 && ch + 1 < 8 && tid == 0) {
            int nb = (ch + 1) & 1;
            unsigned mb = nb ? mb_bm1 : mb_bm0;
            mbar_expect(mb, 20480);
            bulk_g2s(sbase + OFF_BM + nb * 20480,
                     (const char*)g_bm + (size_t)(ch + 1) * 20480, 20480, mb);
        }
        // adj phase for chunk ch (reads gs only)
        #pragma unroll
        for (int r = 0; r < 7; r++) {
            int fc = w + r * 10;
            if (fc < 64) {
                int f = ch * 64 + fc;
                float2 gi = gs[iCh * 517 + f], gj = gs[jCh * 517 + f];
                float u, v;
                if (dg) { u = gi.x*gi.x + gi.y*gi.y;  v = gj.x*gj.x + gj.y*gj.y; }
                else    { u = gi.x*gj.x + gi.y*gj.y;  v = gi.y*gj.x - gi.x*gj.y; }
                adj[fc * 32 + lane] = make_float2(u, v);
            }
        }
        __syncthreads();
        mbar_wait((ch & 1) ? mb_bm1 : mb_bm0, (ch >> 1) & 1);

        const ulonglong2* bmc = (const ulonglong2*)(sm_ + OFF_BM + (ch & 1) * 20480);
        #pragma unroll 4
        for (int fc = 0; fc < 64; fc++) {
            float2 ad = adj[fc * 32 + lane];
            unsigned long long uu = pack2(ad.x, ad.x);
            unsigned long long vv = pack2(ad.y, ad.y);
            ulonglong2 q0 = bmc[fc * 20 + 2 * w];
            ulonglong2 q1 = bmc[fc * 20 + 2 * w + 1];
            fma2(accA0, uu, q0.x); fma2(accB0, vv, q0.x);
            fma2(accA1, uu, q0.y); fma2(accB1, vv, q0.y);
            fma2(accA2, uu, q1.x); fma2(accB2, vv, q1.x);
            fma2(accA3, uu, q1.y); fma2(accB3, vv, q1.y);
        }
    }
    __syncthreads();

    // ---- epilogue: assemble band_cov, dsum, cov->pv projection ----
    float2* bc   = (float2*)(sm_);
    float*  invd = (float*)(sm_ + 20480);
    float2* ct   = (float2*)(sm_ + 20736);   // [64][65]

    {
        unsigned long long A[4]  = {accA0, accA1, accA2, accA3};
        unsigned long long Bv[4] = {accB0, accB1, accB2, accB3};
        #pragma unroll
        for (int kk = 0; kk < 4; kk++) {
            float S1, S3, S4, S2;
            unpack2(A[kk], S1, S3);
            unpack2(Bv[kk], S4, S2);
            int k = 4 * w + kk;
            if (dg) {
                bc[k * 64 + iCh * 9] = make_float2(S1, S3);
                bc[k * 64 + jCh * 9] = make_float2(S4, S2);
            } else {
                bc[k * 64 + iCh * 8 + jCh] = make_float2(S1 - S2, S3 + S4);
                bc[k * 64 + jCh * 8 + iCh] = make_float2(S1 + S2, S3 - S4);
            }
        }
    }
    __syncthreads();

    if (tid < 40) {
        float s = 0.f;
        #pragma unroll
        for (int d = 0; d < 8; d++) s += bc[tid * 64 + d * 9].x;
        invd[tid] = 1.0f / fmaxf(s, 1e-20f);
    }
    for (int idx = tid; idx < 4096; idx += NTHR) {
        int c = idx >> 6, p = idx & 63;
        ct[c * 65 + p] = g_ct[idx];
    }
    __syncthreads();

    const unsigned long long* ctu = (const unsigned long long*)ct;
    const unsigned long long* bcu = (const unsigned long long*)bc;
    const int p  = tid & 63;
    const int kq = tid >> 6;         // 0..4, warp-uniform
    unsigned long long acc[8] = {0,0,0,0,0,0,0,0};
    #pragma unroll 4
    for (int c = 0; c < 64; c++) {
        unsigned long long m = ctu[c * 65 + p];
        #pragma unroll
        for (int r = 0; r < 8; r++)
            fma2(acc[r], m, bcu[(kq + 5 * r) * 64 + c]);
    }
    float* zt = g_z + (size_t)tile * 2560;
    #pragma unroll
    for (int r = 0; r < 8; r++) {
        int k = kq + 5 * r;
        float lo, hi; unpack2(acc[r], lo, hi);
        zt[k * 64 + p] = (lo - hi) * invd[k];   // Re(c2p·y) / dsum
    }
}

// ---- IIR as blocked scan: 16 chunks of 25 frames ----
__global__ void __launch_bounds__(256) iir_local(const float* __restrict__ tau,
                                                 float* __restrict__ out)
{
    int tid = blockIdx.x * 256 + threadIdx.x;   // 81920 = B*16*K*P
    int p = tid & 63;
    int k = (tid >> 6) % 40;
    int ch = (tid / 2560) & 15;
    int b = tid / 40960;
    float a = tau[k], om = 1.0f - a;
    size_t base = ((size_t)b * 400 + ch * 25) * 2560 + k * 64 + p;
    float y = 0.f;
    #pragma unroll 5
    for (int i = 0; i < 25; i++) {
        y = a * y + om * g_z[base + (size_t)i * 2560];
        out[base + (size_t)i * 2560] = y;
    }
    g_cf[((b * 16 + ch) * 40 + k) * 64 + p] = y;
}

__global__ void __launch_bounds__(256) iir_carry(const float* __restrict__ tau)
{
    int tid = blockIdx.x * 256 + threadIdx.x;   // 5120 = B*K*P
    int p = tid & 63, k = (tid >> 6) % 40, b = tid / 2560;
    float a = tau[k];
    float a2 = a * a, a4 = a2 * a2, a8 = a4 * a4, a16 = a8 * a8;
    float a25 = a16 * a8 * a;
    float cf[16];
    #pragma unroll
    for (int ch = 0; ch < 16; ch++)
        cf[ch] = g_cf[((b * 16 + ch) * 40 + k) * 64 + p];
    float prev = 0.f;
    #pragma unroll
    for (int ch = 0; ch < 16; ch++) {
        g_ci[((b * 16 + ch) * 40 + k) * 64 + p] = prev;
        prev = cf[ch] + a25 * prev;
    }
}

__global__ void __launch_bounds__(256) iir_fix(const float* __restrict__ tau,
                                               float* __restrict__ out)
{
    int tid = blockIdx.x * 256 + threadIdx.x;
    int p = tid & 63, k = (tid >> 6) % 40;
    int ch = (tid / 2560) & 15, b = tid / 40960;
    if (ch == 0) return;
    float c = g_ci[((b * 16 + ch) * 40 + k) * 64 + p];
    float a = tau[k];
    size_t base = ((size_t)b * 400 + ch * 25) * 2560 + k * 64 + p;
    float t = a * c;
    #pragma unroll 5
    for (int i = 0; i < 25; i++) {
        out[base + (size_t)i * 2560] += t;   // y = local + c * a^(i+1)
        t *= a;
    }
}

extern "C" void kernel_launch(void* const* d_in, const int* in_sizes, int n_in,
                              void* d_out, int out_size)
{
    const float* br  = (const float*)d_in[0];
    const float* bi  = (const float*)d_in[1];
    const float* bmr = (const float*)d_in[2];
    const float* bmi = (const float*)d_in[3];
    const float* pr  = (const float*)d_in[4];
    const float* pi  = (const float*)d_in[5];
    const float* tau = (const float*)d_in[6];

    cudaFuncSetAttribute(pv_main, cudaFuncAttributeMaxDynamicSharedMemorySize, SMEM_TOTAL);

    prep<<<96, 256>>>(bmr, bmi, pr, pi);
    pv_main<<<TILES, NTHR, SMEM_TOTAL>>>(br, bi);
    iir_local<<<320, 256>>>(tau, (float*)d_out);
    iir_carry<<<20, 256>>>(tau);
    iir_fix<<<320, 256>>>(tau, (float*)d_out);
}

// round 6
// speedup vs baseline: 1.7059x; 1.0827x over previous
#include <cuda_runtime.h>

#define TILES 800
#define NTHR  320   // 10 warps: warp = k-group (4 ks), lane = pair item

__device__ float  g_z[2 * 400 * 40 * 64];   // pre-IIR projected values (B,T,K,P)
__device__ float  g_cf[2 * 16 * 40 * 64];   // chunk-final y
__device__ __align__(16) float2 g_bm[512 * 40];  // interleaved (br,bi) band matrix
__device__ __align__(16) float2 g_ct[64 * 64];   // c2p transposed [c][p]

// item table: bits[0:8)=i, [8:16)=j, bit16 = diag-pseudo-pair flag
__constant__ unsigned PAIR_TBL[32] = {
  0x0100,0x0200,0x0300,0x0400,0x0500,0x0600,0x0700,
  0x0201,0x0301,0x0401,0x0501,0x0601,0x0701,
  0x0302,0x0402,0x0502,0x0602,0x0702,
  0x0403,0x0503,0x0603,0x0703,
  0x0504,0x0604,0x0704,
  0x0605,0x0705,
  0x0706,
  0x10100,0x10302,0x10504,0x10706
};

// ---- smem layout (bytes), total 69984 -> 3 CTAs/SM ----
// [0,33088)       gs float2[8][517]           (epilogue: bc@0 20480 | invd@20480 | ct@20736..54016)
// [33088,49472)   adj double buffer: 2 x 8192 (32f x 32 pairs float2)
// [49472,69952)   bm double buffer:  2 x 10240 (32f x 40k float2)
//   prologue overlay: brs float[4096]@33088, bis float[4096]@49472 (dead before bm chunk0 lands)
// [69952,69984)   mbarriers: mb_x, mb_bm0, mb_bm1
#define OFF_GS   0
#define OFF_ADJ  33088
#define OFF_BM   49472
#define OFF_BRS  33088
#define OFF_BIS  49472
#define OFF_MB   69952
#define SMEM_TOTAL 69984
#define CHUNKS 16          // 32 f each
#define CHUNK_BYTES 10240

__device__ __forceinline__ unsigned long long pack2(float a, float b) {
    unsigned long long r;
    asm("mov.b64 %0, {%1,%2};" : "=l"(r) : "f"(a), "f"(b));
    return r;
}
__device__ __forceinline__ void fma2(unsigned long long& acc,
                                     unsigned long long a, unsigned long long b) {
    asm("fma.rn.f32x2 %0, %1, %2, %0;" : "+l"(acc) : "l"(a), "l"(b));
}
__device__ __forceinline__ void unpack2(unsigned long long x, float& lo, float& hi) {
    asm("mov.b64 {%0,%1}, %2;" : "=f"(lo), "=f"(hi) : "l"(x));
}
__device__ __forceinline__ void mbar_init(unsigned mbar, unsigned cnt) {
    asm volatile("mbarrier.init.shared.b64 [%0], %1;" :: "r"(mbar), "r"(cnt) : "memory");
}
__device__ __forceinline__ void mbar_expect(unsigned mbar, unsigned bytes) {
    asm volatile("mbarrier.arrive.expect_tx.shared.b64 _, [%0], %1;"
                 :: "r"(mbar), "r"(bytes) : "memory");
}
__device__ __forceinline__ void bulk_g2s(unsigned dst, const void* src,
                                         unsigned bytes, unsigned mbar) {
    asm volatile("cp.async.bulk.shared::cluster.global.mbarrier::complete_tx::bytes "
                 "[%0], [%1], %2, [%3];"
                 :: "r"(dst), "l"(src), "r"(bytes), "r"(mbar) : "memory");
}
__device__ __forceinline__ void mbar_wait(unsigned mbar, unsigned parity) {
    asm volatile(
        "{\n\t.reg .pred P1;\n\t"
        "WL_%=:\n\t"
        "mbarrier.try_wait.parity.acquire.cta.shared::cta.b64 P1, [%0], %1, 0x989680;\n\t"
        "@P1 bra.uni WD_%=;\n\t"
        "bra.uni WL_%=;\n\t"
        "WD_%=:\n\t}"
        :: "r"(mbar), "r"(parity) : "memory");
}

extern __shared__ char sm_[];

// ---- prep: build interleaved bm and transposed c2p (runs every launch) ----
__global__ void __launch_bounds__(256) prep(
    const float* __restrict__ bmr, const float* __restrict__ bmi,
    const float* __restrict__ pr,  const float* __restrict__ pi)
{
    int t = blockIdx.x * 256 + threadIdx.x;
    if (t < 20480) {
        g_bm[t] = make_float2(bmr[t], bmi[t]);
    } else {
        int i = t - 20480;
        if (i < 4096) {
            int p = i >> 6, c = i & 63;
            g_ct[c * 64 + p] = make_float2(pr[i], pi[i]);
        }
    }
}

__global__ void __launch_bounds__(NTHR, 3) pv_main(
    const float* __restrict__ br,  const float* __restrict__ bi)
{
    float*  brs = (float*)(sm_ + OFF_BRS);
    float*  bis = (float*)(sm_ + OFF_BIS);
    float2* gs  = (float2*)(sm_ + OFF_GS);
    const unsigned sbase = (unsigned)__cvta_generic_to_shared(sm_);
    const unsigned mb_x   = sbase + OFF_MB;
    const unsigned mb_bm0 = sbase + OFF_MB + 8;
    const unsigned mb_bm1 = sbase + OFF_MB + 16;

    const int tid  = threadIdx.x;
    const int tile = blockIdx.x;
    const int lane = tid & 31;
    const int w    = tid >> 5;           // warp = k-group (k = 4w..4w+3)

    if (tid == 0) {
        mbar_init(mb_x, 1);
        mbar_init(mb_bm0, 1);
        mbar_init(mb_bm1, 1);
        asm volatile("fence.proxy.async.shared::cta;" ::: "memory");
    }
    __syncthreads();
    if (tid == 0) {
        mbar_expect(mb_x, 32768);
        bulk_g2s(sbase + OFF_BRS, br + (size_t)tile * 4096, 16384, mb_x);
        bulk_g2s(sbase + OFF_BIS, bi + (size_t)tile * 4096, 16384, mb_x);
    }
    mbar_wait(mb_x, 0);

    // ---- step 1: per (c,f): (|x|^2, rsqrt) into gs ----
    #pragma unroll
    for (int r = 0; r < 13; r++) {
        int t = tid + r * NTHR;
        if (t < 4096) {
            int c = t >> 9, f = t & 511;
            float re = brs[t], im = bis[t];
            float n = re * re + im * im;
            gs[c * 517 + f] = make_float2(n, rsqrtf(fmaxf(n, 1e-37f)));
        }
    }
    __syncthreads();

    // ---- step 2: trace-normalised amplitude a_c = |x_c| * rsqrt(clip(tr)) ----
    for (int f = tid; f < 512; f += NTHR) {
        float tr = 0.f;
        #pragma unroll
        for (int c = 0; c < 8; c++) tr += gs[c * 517 + f].x;
        float sit = rsqrtf(fmaxf(tr, 1e-20f));
        #pragma unroll
        for (int c = 0; c < 8; c++) {
            float2 v = gs[c * 517 + f];
            gs[c * 517 + f].x = v.x * v.y * sit;   // a = n*rsqrt(n)*sit = |x|*sit
        }
    }
    __syncthreads();

    // ---- step 3: g_c[f] = a_c[f] * r[fm] * r[fp] * conj(x[fm]) * x[fp] ----
    float2 gv[13];
    #pragma unroll
    for (int r = 0; r < 13; r++) {
        int t = tid + r * NTHR;
        if (t < 4096) {
            int c = t >> 9, f = t & 511;
            int fm = min(max(f - 1, 0), 509), fp = fm + 2;
            float a  = gs[c * 517 + f].x;
            float rm = gs[c * 517 + fm].y, rp = gs[c * 517 + fp].y;
            float xmr = brs[c * 512 + fm], xmi = bis[c * 512 + fm];
            float xpr = brs[c * 512 + fp], xpi = bis[c * 512 + fp];
            float tre = xmr * xpr + xmi * xpi;
            float tim = xmr * xpi - xmi * xpr;
            float s = a * rm * rp;
            gv[r] = make_float2(s * tre, s * tim);
        }
    }
    __syncthreads();
    #pragma unroll
    for (int r = 0; r < 13; r++) {
        int t = tid + r * NTHR;
        if (t < 4096) { int c = t >> 9, f = t & 511; gs[c * 517 + f] = gv[r]; }
    }
    __syncthreads();   // brs/bis dead beyond this point -> bm region free
    if (tid == 0) {    // prefetch bm chunk 0 into slot 0
        mbar_expect(mb_bm0, CHUNK_BYTES);
        bulk_g2s(sbase + OFF_BM, (const char*)g_bm, CHUNK_BYTES, mb_bm0);
    }

    // ---- main loop: adj (32-f, double-buffered) + TMA bm ring + packed GEMM ----
    const unsigned e = PAIR_TBL[lane];
    const int iCh = e & 255, jCh = (e >> 8) & 255;
    const bool dg = (e & 0x10000u) != 0;

    unsigned long long accA0=0, accA1=0, accA2=0, accA3=0;
    unsigned long long accB0=0, accB1=0, accB2=0, accB3=0;

    #pragma unroll 1
    for (int ch = 0; ch < CHUNKS; ch++) {
        // adj phase for chunk ch into adj slot ch&1 (reads gs only)
        float2* adjw = (float2*)(sm_ + OFF_ADJ + (ch & 1) * 8192);
        #pragma unroll
        for (int r = 0; r < 4; r++) {
            int fc = w + r * 10;
            if (fc < 32) {
                int f = ch * 32 + fc;
                float2 gi = gs[iCh * 517 + f], gj = gs[jCh * 517 + f];
                float u, v;
                if (dg) { u = gi.x*gi.x + gi.y*gi.y;  v = gj.x*gj.x + gj.y*gj.y; }
                else    { u = gi.x*gj.x + gi.y*gj.y;  v = gi.y*gj.x - gi.x*gj.y; }
                adjw[fc * 32 + lane] = make_float2(u, v);
            }
        }
        __syncthreads();   // adj(ch) visible; gemm(ch-1) done -> bm slot (ch+1)&1 free
        if (ch + 1 < CHUNKS && tid == 0) {
            int nb = (ch + 1) & 1;
            unsigned mb = nb ? mb_bm1 : mb_bm0;
            mbar_expect(mb, CHUNK_BYTES);
            bulk_g2s(sbase + OFF_BM + nb * CHUNK_BYTES,
                     (const char*)g_bm + (size_t)(ch + 1) * CHUNK_BYTES, CHUNK_BYTES, mb);
        }
        mbar_wait((ch & 1) ? mb_bm1 : mb_bm0, (ch >> 1) & 1);

        const ulonglong2* bmc = (const ulonglong2*)(sm_ + OFF_BM + (ch & 1) * CHUNK_BYTES);
        #pragma unroll 4
        for (int fc = 0; fc < 32; fc++) {
            float2 ad = adjw[fc * 32 + lane];
            unsigned long long uu = pack2(ad.x, ad.x);
            unsigned long long vv = pack2(ad.y, ad.y);
            ulonglong2 q0 = bmc[fc * 20 + 2 * w];
            ulonglong2 q1 = bmc[fc * 20 + 2 * w + 1];
            fma2(accA0, uu, q0.x); fma2(accB0, vv, q0.x);
            fma2(accA1, uu, q0.y); fma2(accB1, vv, q0.y);
            fma2(accA2, uu, q1.x); fma2(accB2, vv, q1.x);
            fma2(accA3, uu, q1.y); fma2(accB3, vv, q1.y);
        }
    }
    __syncthreads();

    // ---- epilogue: assemble band_cov, dsum, cov->pv projection ----
    float2* bc   = (float2*)(sm_);
    float*  invd = (float*)(sm_ + 20480);
    float2* ct   = (float2*)(sm_ + 20736);   // [64][65]

    {
        unsigned long long A[4]  = {accA0, accA1, accA2, accA3};
        unsigned long long Bv[4] = {accB0, accB1, accB2, accB3};
        #pragma unroll
        for (int kk = 0; kk < 4; kk++) {
            float S1, S3, S4, S2;
            unpack2(A[kk], S1, S3);
            unpack2(Bv[kk], S4, S2);
            int k = 4 * w + kk;
            if (dg) {
                bc[k * 64 + iCh * 9] = make_float2(S1, S3);
                bc[k * 64 + jCh * 9] = make_float2(S4, S2);
            } else {
                bc[k * 64 + iCh * 8 + jCh] = make_float2(S1 - S2, S3 + S4);
                bc[k * 64 + jCh * 8 + iCh] = make_float2(S1 + S2, S3 - S4);
            }
        }
    }
    __syncthreads();

    if (tid < 40) {
        float s = 0.f;
        #pragma unroll
        for (int d = 0; d < 8; d++) s += bc[tid * 64 + d * 9].x;
        invd[tid] = 1.0f / fmaxf(s, 1e-20f);
    }
    for (int idx = tid; idx < 4096; idx += NTHR) {
        int c = idx >> 6, p = idx & 63;
        ct[c * 65 + p] = g_ct[idx];
    }
    __syncthreads();

    const unsigned long long* ctu = (const unsigned long long*)ct;
    const unsigned long long* bcu = (const unsigned long long*)bc;
    const int p  = tid & 63;
    const int kq = tid >> 6;         // 0..4, warp-uniform
    unsigned long long acc[8] = {0,0,0,0,0,0,0,0};
    #pragma unroll 4
    for (int c = 0; c < 64; c++) {
        unsigned long long m = ctu[c * 65 + p];
        #pragma unroll
        for (int r = 0; r < 8; r++)
            fma2(acc[r], m, bcu[(kq + 5 * r) * 64 + c]);
    }
    float* zt = g_z + (size_t)tile * 2560;
    #pragma unroll
    for (int r = 0; r < 8; r++) {
        int k = kq + 5 * r;
        float lo, hi; unpack2(acc[r], lo, hi);
        zt[k * 64 + p] = (lo - hi) * invd[k];   // Re(c2p·y) / dsum
    }
}

// ---- IIR pass 1: chunk finals only (16 chunks of 25 frames) ----
__global__ void __launch_bounds__(256) iir_pass1(const float* __restrict__ tau)
{
    int tid = blockIdx.x * 256 + threadIdx.x;   // 81920 = B*16*K*P
    int p = tid & 63;
    int k = (tid >> 6) % 40;
    int ch = (tid / 2560) & 15;
    int b = tid / 40960;
    float a = tau[k], om = 1.0f - a;
    size_t base = ((size_t)b * 400 + ch * 25) * 2560 + k * 64 + p;
    float y = 0.f;
    #pragma unroll 5
    for (int i = 0; i < 25; i++)
        y = a * y + om * g_z[base + (size_t)i * 2560];
    g_cf[((b * 16 + ch) * 40 + k) * 64 + p] = y;
}

// ---- IIR pass 2: inline carry combine + full scan, single out write ----
__global__ void __launch_bounds__(256) iir_pass2(const float* __restrict__ tau,
                                                 float* __restrict__ out)
{
    int tid = blockIdx.x * 256 + threadIdx.x;
    int p = tid & 63;
    int k = (tid >> 6) % 40;
    int ch = (tid / 2560) & 15;
    int b = tid / 40960;
    float a = tau[k], om = 1.0f - a;
    float a2 = a * a, a4 = a2 * a2, a8 = a4 * a4, a16 = a8 * a8;
    float a25 = a16 * a8 * a;

    // carry-in = scan of earlier chunk finals (MLP-friendly predicated loads)
    float cf[16];
    #pragma unroll
    for (int j = 0; j < 15; j++)
        cf[j] = (j < ch) ? g_cf[((b * 16 + j) * 40 + k) * 64 + p] : 0.f;
    float y = 0.f;
    #pragma unroll
    for (int j = 0; j < 15; j++)
        if (j < ch) y = cf[j] + a25 * y;

    size_t base = ((size_t)b * 400 + ch * 25) * 2560 + k * 64 + p;
    #pragma unroll 5
    for (int i = 0; i < 25; i++) {
        y = a * y + om * g_z[base + (size_t)i * 2560];
        out[base + (size_t)i * 2560] = y;
    }
}

extern "C" void kernel_launch(void* const* d_in, const int* in_sizes, int n_in,
                              void* d_out, int out_size)
{
    const float* br  = (const float*)d_in[0];
    const float* bi  = (const float*)d_in[1];
    const float* bmr = (const float*)d_in[2];
    const float* bmi = (const float*)d_in[3];
    const float* pr  = (const float*)d_in[4];
    const float* pi  = (const float*)d_in[5];
    const float* tau = (const float*)d_in[6];

    cudaFuncSetAttribute(pv_main, cudaFuncAttributeMaxDynamicSharedMemorySize, SMEM_TOTAL);

    prep<<<96, 256>>>(bmr, bmi, pr, pi);
    pv_main<<<TILES, NTHR, SMEM_TOTAL>>>(br, bi);
    iir_pass1<<<320, 256>>>(tau);
    iir_pass2<<<320, 256>>>(tau, (float*)d_out);
}